// round 13
// baseline (speedup 1.0000x reference)
#include <cuda_runtime.h>

// D2Q9 LBM single step — smem-staged f (bulk uint4 copy), in-place collide,
// smem stream-gather + bounce-back + macro lift.
//   f    [2048,2048,9]  f32
//   rho  [2048,2048]    f32
//   u    [2048,2048,2]  f32 (float2)
//   mask [2048,2048]    bool, dtype unknown (u8/i32/f32) -> runtime detection
//   out  [2048,2048,12] f32  (f_new[9], rho_new, ux, uy)
//
// jnp.roll(a, shift=e) => new[x,y] = old[x-ex, y-ey] (periodic &2047).

#define NXg 2048
#define NYg 2048
#define WRAP(v) ((v) & 2047)

#define TW 64                 // tile width (y, contiguous)
#define TH 8                  // tile height (x)
#define NROWS (TH + 2)        // 10 halo rows
// smem row layout (floats): [ inner 64 cells *9 = 576 | hy=0 edge: 9 | hy=65 edge: 9 ] + pad
#define RSTRIDE 596           // 594 + 2 pad (keeps %4==0 for aligned uint4 stores)
#define EDGE_LO 576           // offset of hy==0 cell within row
#define EDGE_HI 585           // offset of hy==65 cell within row
#define ROW_U4 144            // 576 floats / 4 per inner span
#define NU4 (NROWS * ROW_U4)  // 1440 uint4 copies per CTA

// ---- mask dtype detection (device globals zero-init; atomicOr idempotent) ----
__device__ unsigned int g_byte_flags[4];

__global__ void detect_mask_kernel(const uint4* __restrict__ mask_v) {
    const int nvec = (256 * 1024) / 16;   // scan first 256 KB
    unsigned int loc0 = 0, loc1 = 0, loc2 = 0, loc3 = 0;
    for (int i = blockIdx.x * blockDim.x + threadIdx.x; i < nvec;
         i += gridDim.x * blockDim.x) {
        uint4 v = mask_v[i];
        unsigned int w = v.x | v.y | v.z | v.w;
        loc0 |= (w & 0x000000FFu);
        loc1 |= (w & 0x0000FF00u);
        loc2 |= (w & 0x00FF0000u);
        loc3 |= (w & 0xFF000000u);
    }
    if (loc0) atomicOr(&g_byte_flags[0], 1u);
    if (loc1) atomicOr(&g_byte_flags[1], 1u);
    if (loc2) atomicOr(&g_byte_flags[2], 1u);
    if (loc3) atomicOr(&g_byte_flags[3], 1u);
}

__global__ __launch_bounds__(256, 4)
void lbm_step_kernel(const float*  __restrict__ f,
                     const float*  __restrict__ rho,
                     const float2* __restrict__ u,
                     const void*   __restrict__ mask,
                     float* __restrict__ out)
{
    __shared__ float fs[NROWS * RSTRIDE];   // 5960 floats = 23.84 KB

    const int tid = threadIdx.x;
    const int Y0  = blockIdx.x * TW;
    const int X0  = blockIdx.y * TH;

    // Resolve mask dtype (uniform loads)
    const bool b0  = g_byte_flags[0] != 0;
    const bool b1  = g_byte_flags[1] != 0;
    const bool b23 = (g_byte_flags[2] | g_byte_flags[3]) != 0;
    int mode;
    if (b1 || (b0 && b23)) mode = 0;
    else if (b0)           mode = 1;
    else if (b23)          mode = 2;
    else                   mode = 0;

    // Early mask loads for this thread's 2 output cells
    const int ly  = tid & (TW - 1);
    const int lx0 = tid >> 6;
    bool solid[2];
    #pragma unroll
    for (int cp = 0; cp < 2; cp++) {
        const unsigned cell = (unsigned)(X0 + lx0 + 4 * cp) * NYg + (Y0 + ly);
        if (mode == 0)      solid[cp] = ((const unsigned char*)mask)[cell] != 0;
        else if (mode == 1) solid[cp] = ((const int*)mask)[cell] != 0;
        else                solid[cp] = ((const float*)mask)[cell] != 0.0f;
    }

    // ---- Phase 1: bulk copy inner f spans (aligned uint4, coalesced) ----
    // Row r covers gx = WRAP(X0+r-1), cells gy in [Y0, Y0+64): 576 floats, 16B-aligned.
    #pragma unroll
    for (int k = 0; k < 6; k++) {
        const int idx = k * 256 + tid;
        if (k < 5 || idx < NU4) {
            const int r   = idx / ROW_U4;            // constant div -> mul.hi
            const int col = idx - r * ROW_U4;
            const int gx  = WRAP(X0 + r - 1);
            const size_t basef = ((size_t)gx * NYg + Y0) * 9;   // %4 == 0
            const uint4 v = *reinterpret_cast<const uint4*>(f + basef + col * 4);
            *reinterpret_cast<uint4*>(&fs[r * RSTRIDE + col * 4]) = v;
        }
    }
    __syncthreads();

    const float INV_TAU = 1.0f / 0.6f;
    const int   EXq[9]  = {0, 1, 0, -1,  0, 1, -1, -1,  1};
    const int   EYq[9]  = {0, 0, 1,  0, -1, 1,  1, -1, -1};
    const float Wq[9]   = {4.0f/9.0f,
                           1.0f/9.0f, 1.0f/9.0f, 1.0f/9.0f, 1.0f/9.0f,
                           1.0f/36.0f, 1.0f/36.0f, 1.0f/36.0f, 1.0f/36.0f};
    const int   OPPq[9] = {0, 3, 4, 1, 2, 7, 8, 5, 6};

    // ---- Phase 2a: collide in place (inner cells from smem, edges from gmem) ----
    // inner: 640 cells, ids 0..639: r=c>>6, cy=c&63 (no divisions)
    #pragma unroll
    for (int k = 0; k < 3; k++) {
        const int c = k * 256 + tid;
        if (c < 640) {
            const int r  = c >> 6;
            const int cy = c & 63;
            const int gx = WRAP(X0 + r - 1);
            const unsigned gc = (unsigned)gx * NYg + (Y0 + cy);
            const float  rr = rho[gc];
            const float2 uv = u[gc];
            const float  usq = uv.x * uv.x + uv.y * uv.y;
            const int base = r * RSTRIDE + cy * 9;
            #pragma unroll
            for (int q = 0; q < 9; q++) {
                const float fv = fs[base + q];
                const float eu = (float)EXq[q] * uv.x + (float)EYq[q] * uv.y;
                const float feq = Wq[q] * rr *
                                  (1.0f + 3.0f * eu + 4.5f * eu * eu - 1.5f * usq);
                fs[base + q] = fv - (fv - feq) * INV_TAU;
            }
        } else if (c < 660) {
            // edge cells: e = c-640 in 0..19 -> row r=e>>1, side=e&1 (hy 0 or 65)
            const int e    = c - 640;
            const int r    = e >> 1;
            const int side = e & 1;
            const int gx = WRAP(X0 + r - 1);
            const int gy = WRAP(side ? (Y0 + TW) : (Y0 - 1));
            const unsigned gc = (unsigned)gx * NYg + gy;
            const float  rr = rho[gc];
            const float2 uv = u[gc];
            const float  usq = uv.x * uv.x + uv.y * uv.y;
            const int base = r * RSTRIDE + (side ? EDGE_HI : EDGE_LO);
            const float* fc = f + (size_t)gc * 9;
            #pragma unroll
            for (int q = 0; q < 9; q++) {
                const float fv = fc[q];
                const float eu = (float)EXq[q] * uv.x + (float)EYq[q] * uv.y;
                const float feq = Wq[q] * rr *
                                  (1.0f + 3.0f * eu + 4.5f * eu * eu - 1.5f * usq);
                fs[base + q] = fv - (fv - feq) * INV_TAU;
            }
        }
    }
    __syncthreads();

    // ---- Phase 2b: stream-gather from smem + bounce-back + macro + stores ----
    // y-offset within a row, per EY class (edge slots handled by select):
    const int offY_p = (ly == 0)      ? EDGE_LO : (ly - 1) * 9;  // EY=+1: hy=ly
    const int offY_0 = ly * 9;                                    // EY= 0: hy=ly+1
    const int offY_m = (ly == TW - 1) ? EDGE_HI : (ly + 1) * 9;  // EY=-1: hy=ly+2
    const int offY[3] = {offY_p, offY_0, offY_m};                 // index 1-EY

    #pragma unroll
    for (int cp = 0; cp < 2; cp++) {
        const int lx = lx0 + 4 * cp;
        const unsigned cell = (unsigned)(X0 + lx) * NYg + (Y0 + ly);

        float fn[9];
        if (solid[cp]) {
            const int base = (lx + 1) * RSTRIDE + ly * 9;
            #pragma unroll
            for (int q = 0; q < 9; q++) fn[q] = fs[base + OPPq[q]];
        } else {
            #pragma unroll
            for (int q = 0; q < 9; q++)
                fn[q] = fs[(lx + 1 - EXq[q]) * RSTRIDE + offY[1 - EYq[q]] + q];
        }

        float rn = 0.0f;
        #pragma unroll
        for (int q = 0; q < 9; q++) rn += fn[q];
        const float uxn = (fn[1] - fn[3]) + (fn[5] - fn[6]) + (fn[8] - fn[7]);
        const float uyn = (fn[2] - fn[4]) + (fn[5] + fn[6]) - (fn[7] + fn[8]);
        const float inv_rn = 1.0f / rn;

        float4* op = reinterpret_cast<float4*>(out + (size_t)cell * 12);
        op[0] = make_float4(fn[0], fn[1], fn[2], fn[3]);
        op[1] = make_float4(fn[4], fn[5], fn[6], fn[7]);
        op[2] = make_float4(fn[8], rn, uxn * inv_rn, uyn * inv_rn);
    }
}

extern "C" void kernel_launch(void* const* d_in, const int* in_sizes, int n_in,
                              void* d_out, int out_size)
{
    const float*  f    = (const float*)d_in[0];
    const float*  rho  = (const float*)d_in[1];
    const float2* u    = (const float2*)d_in[2];
    const void*   mask = d_in[3];
    float*        out  = (float*)d_out;

    detect_mask_kernel<<<32, 256>>>((const uint4*)mask);

    dim3 block(256);
    dim3 grid(NYg / TW, NXg / TH);   // 32 x 256 = 8192 CTAs
    lbm_step_kernel<<<grid, block>>>(f, rho, u, mask, out);
}

// round 14
// speedup vs baseline: 1.0437x; 1.0437x over previous
#include <cuda_runtime.h>

// D2Q9 LBM single step — single-kernel, single-barrier design.
//   Phase 1: stream f tile rows (aligned uint4) + per-cell collide coeffs
//            (A=rho*(1-1.5u^2), B=3rho, ux, uy) into smem.
//   Phase 2: stream-gather + collide-at-gather + bounce-back + macro + store.
// Mask: proven 4-byte (int32 or float32) in R5/R6 A-B test; nonzero == solid
// under both encodings, so read as uint32 — no detection kernel needed.
//
//   f    [2048,2048,9]  f32      rho [2048,2048] f32
//   u    [2048,2048,2]  f32      mask[2048,2048] 4-byte bool
//   out  [2048,2048,12] f32  (f_new[9], rho_new, ux, uy)
// jnp.roll(a, shift=e) => new[x,y] = old[x-ex, y-ey] (periodic &2047).

#define NXg 2048
#define NYg 2048
#define WRAP(v) ((v) & 2047)

#define TW 64                 // tile width (y, contiguous)
#define TH 8                  // tile height (x)
#define NROWS (TH + 2)        // 10 halo rows
// f smem row: [inner 64 cells * 9 = 576 | hy=0 edge: 9 | hy=65 edge: 9] + pad
#define RSTRIDE 596
#define EDGE_LO 576
#define EDGE_HI 585
#define ROW_U4 144            // uint4 copies per inner row span
#define NU4 (NROWS * ROW_U4)  // 1440
#define CW 66                 // coeff row width (indexed by true hy 0..65)

__global__ __launch_bounds__(256, 4)
void lbm_step_kernel(const float*        __restrict__ f,
                     const float*        __restrict__ rho,
                     const float2*       __restrict__ u,
                     const unsigned int* __restrict__ mask,
                     float*              __restrict__ out)
{
    __shared__ float  fs[NROWS * RSTRIDE];   // raw f tile+halo      23.84 KB
    __shared__ float4 cs[NROWS * CW];        // per-cell coeffs      10.56 KB

    const int tid = threadIdx.x;
    const int Y0  = blockIdx.x * TW;
    const int X0  = blockIdx.y * TH;
    const int ly  = tid & 63;
    const int lx0 = tid >> 6;

    // Mask loads first (latency hidden behind phase 1)
    bool solid[2];
    #pragma unroll
    for (int cp = 0; cp < 2; cp++) {
        const unsigned cell = (unsigned)(X0 + lx0 + 4 * cp) * NYg + (Y0 + ly);
        solid[cp] = (mask[cell] != 0u);
    }

    // ---- Phase 1a: bulk f copy (aligned uint4, perfectly coalesced) ----
    #pragma unroll
    for (int k = 0; k < 6; k++) {
        const int idx = k * 256 + tid;
        if (k < 5 || idx < NU4) {
            const int r   = idx / ROW_U4;        // constant div -> mul.hi
            const int col = idx - r * ROW_U4;
            const int gx  = WRAP(X0 + r - 1);
            const size_t basef = ((size_t)gx * NYg + Y0) * 9;   // 16B aligned
            const uint4 v = *reinterpret_cast<const uint4*>(f + basef + col * 4);
            *reinterpret_cast<uint4*>(&fs[r * RSTRIDE + col * 4]) = v;
        }
    }

    // ---- Phase 1b: per-cell collide coefficients (+ edge-cell f) ----
    #pragma unroll
    for (int k = 0; k < 3; k++) {
        const int c = k * 256 + tid;
        if (c < 640) {
            const int r = c >> 6, cy = c & 63;
            const int gx = WRAP(X0 + r - 1);
            const unsigned gc = (unsigned)gx * NYg + (Y0 + cy);
            const float  rr = rho[gc];
            const float2 uv = u[gc];
            const float usq = uv.x * uv.x + uv.y * uv.y;
            cs[r * CW + cy + 1] =
                make_float4(rr * (1.0f - 1.5f * usq), 3.0f * rr, uv.x, uv.y);
        } else if (c < 660) {
            const int e = c - 640, r = e >> 1, side = e & 1;
            const int gx = WRAP(X0 + r - 1);
            const int gy = WRAP(side ? (Y0 + TW) : (Y0 - 1));
            const unsigned gc = (unsigned)gx * NYg + gy;
            const float  rr = rho[gc];
            const float2 uv = u[gc];
            const float usq = uv.x * uv.x + uv.y * uv.y;
            cs[r * CW + (side ? 65 : 0)] =
                make_float4(rr * (1.0f - 1.5f * usq), 3.0f * rr, uv.x, uv.y);
            const float* fc = f + (size_t)gc * 9;
            const int base = r * RSTRIDE + (side ? EDGE_HI : EDGE_LO);
            #pragma unroll
            for (int q = 0; q < 9; q++) fs[base + q] = fc[q];
        }
    }
    __syncthreads();   // the ONLY barrier

    // ---- Phase 2: gather + collide + bounce-back + macro + store ----
    const int   EXq[9]  = {0, 1, 0, -1,  0, 1, -1, -1,  1};
    const int   EYq[9]  = {0, 0, 1,  0, -1, 1,  1, -1, -1};
    const float Wq[9]   = {4.0f/9.0f,
                           1.0f/9.0f, 1.0f/9.0f, 1.0f/9.0f, 1.0f/9.0f,
                           1.0f/36.0f, 1.0f/36.0f, 1.0f/36.0f, 1.0f/36.0f};
    const int   OPPq[9] = {0, 3, 4, 1, 2, 7, 8, 5, 6};
    const float INV_TAU = 1.0f / 0.6f;
    const float CREM    = 1.0f - INV_TAU;

    // per-EY-class y offsets inside an f row (edge slots via select)
    const int offY_p = (ly == 0)  ? EDGE_LO : (ly - 1) * 9;  // EY=+1 (hy=ly)
    const int offY_0 = ly * 9;                                // EY= 0 (hy=ly+1)
    const int offY_m = (ly == 63) ? EDGE_HI : (ly + 1) * 9;  // EY=-1 (hy=ly+2)
    const int offY[3] = {offY_p, offY_0, offY_m};

    #pragma unroll
    for (int cp = 0; cp < 2; cp++) {
        const int lx = lx0 + 4 * cp;
        const unsigned cell = (unsigned)(X0 + lx) * NYg + (Y0 + ly);
        const bool  sol = solid[cp];
        const float sgn = sol ? -1.0f : 1.0f;
        const int selfRow = lx + 1;
        const int fo_self = selfRow * RSTRIDE + ly * 9;
        const int co_self = selfRow * CW + (ly + 1);

        float fn[9];
        #pragma unroll
        for (int q = 0; q < 9; q++) {
            const int dx = EXq[q], dy = EYq[q];
            const int fo = sol ? (fo_self + OPPq[q])
                               : ((selfRow - dx) * RSTRIDE + offY[1 - dy] + q);
            const int co = sol ? co_self
                               : ((selfRow - dx) * CW + (ly + 1 - dy));
            const float  fv = fs[fo];
            const float4 cc = cs[co];
            // feq = A + t + 1.5*t*eu,  t = B*eu ;  fn = (1-1/tau)*fv + (w/tau)*feq
            const float eu  = sgn * ((float)dx * cc.z + (float)dy * cc.w);
            const float t   = cc.y * eu;
            const float feq = cc.x + t + 1.5f * t * eu;
            fn[q] = CREM * fv + (Wq[q] * INV_TAU) * feq;
        }

        float rn = 0.0f;
        #pragma unroll
        for (int q = 0; q < 9; q++) rn += fn[q];
        const float uxn = (fn[1] - fn[3]) + (fn[5] - fn[6]) + (fn[8] - fn[7]);
        const float uyn = (fn[2] - fn[4]) + (fn[5] + fn[6]) - (fn[7] + fn[8]);
        const float inv_rn = 1.0f / rn;

        float4* op = reinterpret_cast<float4*>(out + (size_t)cell * 12);
        op[0] = make_float4(fn[0], fn[1], fn[2], fn[3]);
        op[1] = make_float4(fn[4], fn[5], fn[6], fn[7]);
        op[2] = make_float4(fn[8], rn, uxn * inv_rn, uyn * inv_rn);
    }
}

extern "C" void kernel_launch(void* const* d_in, const int* in_sizes, int n_in,
                              void* d_out, int out_size)
{
    const float*        f    = (const float*)d_in[0];
    const float*        rho  = (const float*)d_in[1];
    const float2*       u    = (const float2*)d_in[2];
    const unsigned int* mask = (const unsigned int*)d_in[3];
    float*              out  = (float*)d_out;

    dim3 block(256);
    dim3 grid(NYg / TW, NXg / TH);   // 32 x 256 = 8192 CTAs
    lbm_step_kernel<<<grid, block>>>(f, rho, u, mask, out);
}

// round 15
// speedup vs baseline: 1.0682x; 1.0235x over previous
#include <cuda_runtime.h>

// D2Q9 LBM single step — single-kernel, single-barrier, occupancy-tuned.
//   Phase 1: stream f tile rows (aligned uint4) + per-cell rho/u into smem.
//   Phase 2: stream-gather + collide-at-gather + bounce-back + macro + store.
// Mask proven 4-byte (R5/R6 A-B test): nonzero == solid for both int32/f32.
//
//   f    [2048,2048,9]  f32      rho [2048,2048] f32
//   u    [2048,2048,2]  f32      mask[2048,2048] 4-byte bool
//   out  [2048,2048,12] f32  (f_new[9], rho_new, ux, uy)
// jnp.roll(a, shift=e) => new[x,y] = old[x-ex, y-ey] (periodic &2047).

#define NXg 2048
#define NYg 2048
#define WRAP(v) ((v) & 2047)

#define TW 64                 // tile width (y, contiguous)
#define TH 8                  // tile height (x)
#define NROWS (TH + 2)        // 10 halo rows
// f smem row: [inner 64 cells * 9 = 576 | hy=0 edge: 9 | hy=65 edge: 9] + pad
#define RSTRIDE 596
#define EDGE_LO 576
#define EDGE_HI 585
#define ROW_U4 144            // uint4 copies per inner row span
#define NU4 (NROWS * ROW_U4)  // 1440
#define CW 66                 // coeff row width (true halo coord hy 0..65)

__global__ __launch_bounds__(256, 6)
void lbm_step_kernel(const float*        __restrict__ f,
                     const float*        __restrict__ rho,
                     const float2*       __restrict__ u,
                     const unsigned int* __restrict__ mask,
                     float*              __restrict__ out)
{
    __shared__ float  fs[NROWS * RSTRIDE];   // raw f tile+halo   23.84 KB
    __shared__ float  rS[NROWS * CW];        // rho                2.64 KB
    __shared__ float2 uS[NROWS * CW];        // u                  5.28 KB

    const int tid = threadIdx.x;
    const int Y0  = blockIdx.x * TW;
    const int X0  = blockIdx.y * TH;
    const int ly  = tid & 63;
    const int lx0 = tid >> 6;

    // Mask loads first (latency hidden behind phase 1)
    bool solid[2];
    #pragma unroll
    for (int cp = 0; cp < 2; cp++) {
        const unsigned cell = (unsigned)(X0 + lx0 + 4 * cp) * NYg + (Y0 + ly);
        solid[cp] = (mask[cell] != 0u);
    }

    // ---- Phase 1a: bulk f copy (aligned uint4, perfectly coalesced) ----
    #pragma unroll
    for (int k = 0; k < 6; k++) {
        const int idx = k * 256 + tid;
        if (k < 5 || idx < NU4) {
            const int r   = idx / ROW_U4;        // constant div -> mul.hi
            const int col = idx - r * ROW_U4;
            const int gx  = WRAP(X0 + r - 1);
            const size_t basef = ((size_t)gx * NYg + Y0) * 9;   // 16B aligned
            const uint4 v = *reinterpret_cast<const uint4*>(f + basef + col * 4);
            *reinterpret_cast<uint4*>(&fs[r * RSTRIDE + col * 4]) = v;
        }
    }

    // ---- Phase 1b: per-cell rho/u (+ edge-cell f) ----
    #pragma unroll
    for (int k = 0; k < 3; k++) {
        const int c = k * 256 + tid;
        if (c < 640) {
            const int r = c >> 6, cy = c & 63;
            const int gx = WRAP(X0 + r - 1);
            const unsigned gc = (unsigned)gx * NYg + (Y0 + cy);
            rS[r * CW + cy + 1] = rho[gc];
            uS[r * CW + cy + 1] = u[gc];
        } else if (c < 660) {
            const int e = c - 640, r = e >> 1, side = e & 1;
            const int gx = WRAP(X0 + r - 1);
            const int gy = WRAP(side ? (Y0 + TW) : (Y0 - 1));
            const unsigned gc = (unsigned)gx * NYg + gy;
            rS[r * CW + (side ? 65 : 0)] = rho[gc];
            uS[r * CW + (side ? 65 : 0)] = u[gc];
            const float* fc = f + (size_t)gc * 9;
            const int base = r * RSTRIDE + (side ? EDGE_HI : EDGE_LO);
            #pragma unroll
            for (int q = 0; q < 9; q++) fs[base + q] = fc[q];
        }
    }
    __syncthreads();   // the ONLY barrier

    // ---- Phase 2: gather + collide + bounce-back + macro + store ----
    const int   EXq[9]  = {0, 1, 0, -1,  0, 1, -1, -1,  1};
    const int   EYq[9]  = {0, 0, 1,  0, -1, 1,  1, -1, -1};
    const float Wq[9]   = {4.0f/9.0f,
                           1.0f/9.0f, 1.0f/9.0f, 1.0f/9.0f, 1.0f/9.0f,
                           1.0f/36.0f, 1.0f/36.0f, 1.0f/36.0f, 1.0f/36.0f};
    const int   OPPq[9] = {0, 3, 4, 1, 2, 7, 8, 5, 6};
    const float INV_TAU = 1.0f / 0.6f;
    const float CREM    = 1.0f - INV_TAU;

    // fs y-offsets per EY class (edge slots via select); cs uses hy directly
    const int offY[3] = { (ly == 0)  ? EDGE_LO : (ly - 1) * 9,   // EY=+1
                          ly * 9,                                 // EY= 0
                          (ly == 63) ? EDGE_HI : (ly + 1) * 9 }; // EY=-1

    #pragma unroll
    for (int cp = 0; cp < 2; cp++) {
        const int lx = lx0 + 4 * cp;
        const unsigned cell = (unsigned)(X0 + lx) * NYg + (Y0 + ly);
        const bool  sol = solid[cp];
        const float sgn = sol ? -1.0f : 1.0f;

        // row bases: src row = lx+1-dx -> index j=1-dx gives (lx+j)
        const int rowB[3]  = { lx * RSTRIDE, (lx + 1) * RSTRIDE, (lx + 2) * RSTRIDE };
        const int cRowB[3] = { lx * CW,      (lx + 1) * CW,      (lx + 2) * CW };
        const int fo_self  = (lx + 1) * RSTRIDE + ly * 9;
        const int co_self  = (lx + 1) * CW + (ly + 1);

        float fn[9];
        #pragma unroll
        for (int q = 0; q < 9; q++) {
            const int dx = EXq[q], dy = EYq[q];
            const int fo = sol ? (fo_self + OPPq[q])
                               : (rowB[1 - dx] + offY[1 - dy] + q);
            const int co = sol ? co_self
                               : (cRowB[1 - dx] + (ly + 1 - dy));
            const float  fv = fs[fo];
            const float  rr = rS[co];
            const float2 uv = uS[co];
            // feq = rr*(1-1.5usq) + t + 1.5*t*eu,  t = 3*rr*eu
            const float eu  = sgn * ((float)dx * uv.x + (float)dy * uv.y);
            const float usq = uv.x * uv.x + uv.y * uv.y;
            const float t   = 3.0f * rr * eu;
            const float feq = rr - 1.5f * rr * usq + t + 1.5f * t * eu;
            fn[q] = CREM * fv + (Wq[q] * INV_TAU) * feq;
        }

        float rn = 0.0f;
        #pragma unroll
        for (int q = 0; q < 9; q++) rn += fn[q];
        const float uxn = (fn[1] - fn[3]) + (fn[5] - fn[6]) + (fn[8] - fn[7]);
        const float uyn = (fn[2] - fn[4]) + (fn[5] + fn[6]) - (fn[7] + fn[8]);
        const float inv_rn = 1.0f / rn;

        float4* op = reinterpret_cast<float4*>(out + (size_t)cell * 12);
        op[0] = make_float4(fn[0], fn[1], fn[2], fn[3]);
        op[1] = make_float4(fn[4], fn[5], fn[6], fn[7]);
        op[2] = make_float4(fn[8], rn, uxn * inv_rn, uyn * inv_rn);
    }
}

extern "C" void kernel_launch(void* const* d_in, const int* in_sizes, int n_in,
                              void* d_out, int out_size)
{
    const float*        f    = (const float*)d_in[0];
    const float*        rho  = (const float*)d_in[1];
    const float2*       u    = (const float2*)d_in[2];
    const unsigned int* mask = (const unsigned int*)d_in[3];
    float*              out  = (float*)d_out;

    dim3 block(256);
    dim3 grid(NYg / TW, NXg / TH);   // 32 x 256 = 8192 CTAs
    lbm_step_kernel<<<grid, block>>>(f, rho, u, mask, out);
}